// round 14
// baseline (speedup 1.0000x reference)
#include <cuda_runtime.h>
#include <cuda_fp16.h>
#include <cstdint>
#include <math.h>

// ---------------- problem constants ----------------
#define T_DIM 512
#define B_DIM 64
#define E_DIM 300
#define H_DIM 800
#define H2    (H_DIM / 2)        // 400 half2 pairs
#define L_DIM 3
#define M_DIM (T_DIM * B_DIM)   // 32768
#define N_OUT 2400              // 3*H
#define N_PADROWS 2432          // N padded to mult of 128
#define KPAD0 320               // 300 -> mult of 64
#define KPAD  832               // 800 -> mult of 64

// fused scan: 8 j-quads (2 j2 each) x 32 t-chunks of 16
#define SJQ 8                   // uint2 lanes (each covers 2 j2 = 4 j)
#define SCH 32
#define STC (T_DIM / SCH)       // 16

// GEMM tiling
#define BM 128
#define BN 128
#define BK 64
#define STAGES 3
#define STAGE_BYTES 32768       // A 16K | B 16K
#define A_OFF  0
#define B_OFF  16384

// ---------------- static scratch ----------------
__device__ __half g_buf[(size_t)M_DIM * N_OUT];           // post-activation z|f|o (fp16)
__device__ __half A0_buf[(size_t)M_DIM * KPAD0];          // layer0 A operand
__device__ __half A12_buf[(size_t)M_DIM * KPAD];          // layers 1/2 A operand (h); padding stays 0
__device__ __half W0_buf[(size_t)N_PADROWS * KPAD0];
__device__ __half W1_buf[(size_t)N_PADROWS * KPAD];
__device__ __half W2_buf[(size_t)N_PADROWS * KPAD];

// ---------------- helpers ----------------
__device__ __forceinline__ uint32_t smem_u32(const void* p) {
    uint32_t a;
    asm("{ .reg .u64 t; cvta.to.shared.u64 t, %1; cvt.u32.u64 %0, t; }" : "=r"(a) : "l"(p));
    return a;
}
__device__ __forceinline__ void cp16(uint32_t dst, const void* src) {
    asm volatile("cp.async.cg.shared.global [%0], [%1], 16;" :: "r"(dst), "l"(src) : "memory");
}
__device__ __forceinline__ void cp_commit() {
    asm volatile("cp.async.commit_group;" ::: "memory");
}
template <int N> __device__ __forceinline__ void cp_wait() {
    asm volatile("cp.async.wait_group %0;" :: "n"(N) : "memory");
}
__device__ __forceinline__ void ldsm4(uint32_t& r0, uint32_t& r1, uint32_t& r2, uint32_t& r3,
                                      uint32_t addr) {
    asm volatile("ldmatrix.sync.aligned.m8n8.x4.shared.b16 {%0,%1,%2,%3}, [%4];"
                 : "=r"(r0), "=r"(r1), "=r"(r2), "=r"(r3) : "r"(addr));
}
__device__ __forceinline__ void mma_f16(float* c, const uint32_t* a, const uint32_t* b) {
    asm volatile(
        "mma.sync.aligned.m16n8k16.row.col.f32.f16.f16.f32 "
        "{%0,%1,%2,%3}, {%4,%5,%6,%7}, {%8,%9}, {%0,%1,%2,%3};"
        : "+f"(c[0]), "+f"(c[1]), "+f"(c[2]), "+f"(c[3])
        : "r"(a[0]), "r"(a[1]), "r"(a[2]), "r"(a[3]), "r"(b[0]), "r"(b[1]));
}

// f16x2 fast activations (1 MUFU per 2 elements)
__device__ __forceinline__ uint32_t tanh_h2(uint32_t x) {
    uint32_t r;
    asm("tanh.approx.f16x2 %0, %1;" : "=r"(r) : "r"(x));
    return r;
}
__device__ __forceinline__ uint32_t pack_h2(float a, float b) {
    __half2 h = __floats2half2_rn(a, b);
    return *reinterpret_cast<uint32_t*>(&h);
}
// sigmoid(x) = 0.5*tanh(0.5x) + 0.5 (exact identity)
__device__ __forceinline__ uint32_t sigmoid_h2(uint32_t x) {
    const __half2 half_c = __floats2half2_rn(0.5f, 0.5f);
    __half2 xh = *reinterpret_cast<__half2*>(&x);
    __half2 t = __hmul2(xh, half_c);
    uint32_t tu = tanh_h2(*reinterpret_cast<uint32_t*>(&t));
    __half2 th = *reinterpret_cast<__half2*>(&tu);
    __half2 r = __hfma2(th, half_c, half_c);
    return *reinterpret_cast<uint32_t*>(&r);
}
__device__ __forceinline__ float2 h2lo(uint2 v) {
    return __half22float2(*reinterpret_cast<__half2*>(&v.x));
}
__device__ __forceinline__ float2 h2hi(uint2 v) {
    return __half22float2(*reinterpret_cast<__half2*>(&v.y));
}

// ---------------- weight transpose fp16 (all 3 layers in one launch) ----------------
__global__ void conv_w_all_kernel(const float* __restrict__ W0, const float* __restrict__ W1,
                                  const float* __restrict__ W2,
                                  __half* __restrict__ T0, __half* __restrict__ T1,
                                  __half* __restrict__ T2) {
    __shared__ float tile[32][33];
    int layer = blockIdx.z;
    const float* W = (layer == 0) ? W0 : (layer == 1) ? W1 : W2;
    __half* Tw = (layer == 0) ? T0 : (layer == 1) ? T1 : T2;
    int K = (layer == 0) ? E_DIM : H_DIM;
    int Kp = (layer == 0) ? KPAD0 : KPAD;
    int kb = blockIdx.y * 32, nb = blockIdx.x * 32;
    if (kb >= Kp) return;
    for (int r = threadIdx.y; r < 32; r += 8) {
        int k = kb + r, n = nb + threadIdx.x;
        tile[r][threadIdx.x] = (k < K && n < N_OUT) ? W[(size_t)k * N_OUT + n] : 0.f;
    }
    __syncthreads();
    for (int r = threadIdx.y; r < 32; r += 8) {
        int n = nb + r, k = kb + threadIdx.x;
        Tw[(size_t)n * Kp + k] = __float2half(tile[threadIdx.x][r]);
    }
}

// ---------------- sent fp32 -> fp16 (padded K), vectorized ----------------
__global__ void conv_sent_kernel(const float* __restrict__ x) {
    int i = blockIdx.x * 256 + threadIdx.x;
    if (i >= M_DIM * (KPAD0 / 4)) return;
    int row = i / (KPAD0 / 4);
    int j4 = (i % (KPAD0 / 4)) * 4;
    uint2 outv;
    if (j4 < E_DIM) {
        float4 v = *reinterpret_cast<const float4*>(x + (size_t)row * E_DIM + j4);
        __half2 h0 = __floats2half2_rn(v.x, v.y);
        __half2 h1 = __floats2half2_rn(v.z, v.w);
        outv.x = *reinterpret_cast<uint32_t*>(&h0);
        outv.y = *reinterpret_cast<uint32_t*>(&h1);
    } else {
        outv.x = 0u; outv.y = 0u;
    }
    *reinterpret_cast<uint2*>(&A0_buf[(size_t)row * KPAD0 + j4]) = outv;
}

// ---------------- fp16 HMMA GEMM (128x128 tile, BK=64), hoisted addressing ----------
__global__ __launch_bounds__(256, 2)
void qrnn_gemm_kernel(const __half* __restrict__ A, const __half* __restrict__ B,
                      int ldk, int nc,
                      const float* __restrict__ bias, __half* __restrict__ C) {
    extern __shared__ char smem[];
    const uint32_t sbase = smem_u32(smem);

    const int tid = threadIdx.x;
    const int lane = tid & 31;
    const int wid = tid >> 5;
    const int wm = wid >> 2;
    const int wn = wid & 3;
    const int am0 = blockIdx.y * BM;
    const int bn0 = blockIdx.x * BN;

    uint32_t ld_soff[4];
    uint32_t ld_goffA[4];
    uint32_t ld_goffB[4];
#pragma unroll
    for (int i = 0; i < 4; i++) {
        int id = tid + i * 256;
        int row = id >> 3, c = id & 7;
        int sc = c ^ (row & 7);
        ld_soff[i] = row * 128 + sc * 16;
        ld_goffA[i] = (uint32_t)((am0 + row) * ldk + c * 8);
        ld_goffB[i] = (uint32_t)((bn0 + row) * ldk + c * 8);
    }

    auto load_stage = [&](int kc, int st) {
        const uint32_t kof = (uint32_t)kc * BK;
        uint32_t sb = sbase + st * STAGE_BYTES;
#pragma unroll
        for (int i = 0; i < 4; i++) {
            cp16(sb + A_OFF + ld_soff[i], A + ld_goffA[i] + kof);
            cp16(sb + B_OFF + ld_soff[i], B + ld_goffB[i] + kof);
        }
    };

    const int lr = lane & 15;
    const int lc = lane >> 4;
    uint32_t swz[4];
#pragma unroll
    for (int kk = 0; kk < 4; kk++)
        swz[kk] = (uint32_t)(((kk * 2 + lc) ^ (lr & 7)) * 16);
    const uint32_t rowbaseA = (uint32_t)((wm * 64 + lr) * 128);
    const uint32_t rowbaseB = (uint32_t)((wn * 32 + lr) * 128);

    float acc[4][4][4];
#pragma unroll
    for (int i = 0; i < 4; i++)
#pragma unroll
        for (int j = 0; j < 4; j++)
#pragma unroll
            for (int q = 0; q < 4; q++) acc[i][j][q] = 0.f;

    load_stage(0, 0); cp_commit();
    if (nc > 1) { load_stage(1, 1); cp_commit(); }

    int st_cur = 0, st_pre = 2;
    for (int kc = 0; kc < nc; kc++) {
        if (kc + 1 < nc) cp_wait<1>(); else cp_wait<0>();
        __syncthreads();
        if (kc + 2 < nc) {
            load_stage(kc + 2, st_pre); cp_commit();
        }

        const uint32_t sbA = sbase + st_cur * STAGE_BYTES + A_OFF + rowbaseA;
        const uint32_t sbB = sbase + st_cur * STAGE_BYTES + B_OFF + rowbaseB;
        if (++st_cur == STAGES) st_cur = 0;
        if (++st_pre == STAGES) st_pre = 0;

#pragma unroll
        for (int kp = 0; kp < 2; kp++) {
            uint32_t breg[2][4][2];
#pragma unroll
            for (int kk2 = 0; kk2 < 2; kk2++) {
                const uint32_t sw = swz[kp * 2 + kk2];
#pragma unroll
                for (int p = 0; p < 2; p++) {
                    uint32_t r0, r1, r2, r3;
                    ldsm4(r0, r1, r2, r3, sbB + p * 2048 + sw);
                    breg[kk2][2 * p][0] = r0; breg[kk2][2 * p + 1][0] = r1;
                    breg[kk2][2 * p][1] = r2; breg[kk2][2 * p + 1][1] = r3;
                }
            }
#pragma unroll
            for (int kk2 = 0; kk2 < 2; kk2++) {
                const uint32_t sw = swz[kp * 2 + kk2];
#pragma unroll
                for (int mt = 0; mt < 4; mt++) {
                    uint32_t a[4];
                    ldsm4(a[0], a[1], a[2], a[3], sbA + mt * 2048 + sw);
#pragma unroll
                    for (int ng = 0; ng < 4; ng++)
                        mma_f16(acc[mt][ng], a, breg[kk2][ng]);
                }
            }
        }
    }

    // ---- epilogue: bias + f16x2 activation, half2 stores ----
    const int tg = lane >> 2;
    const int tq = lane & 3;
#pragma unroll
    for (int ng = 0; ng < 4; ng++) {
        int colb = bn0 + wn * 32 + ng * 8;
        if (colb >= N_OUT) continue;
        int col = colb + tq * 2;
        float2 bv = *reinterpret_cast<const float2*>(&bias[col]);
        bool is_t = colb < H_DIM;
#pragma unroll
        for (int mt = 0; mt < 4; mt++) {
            int r0 = am0 + wm * 64 + mt * 16 + tg;
            uint32_t p0 = pack_h2(acc[mt][ng][0] + bv.x, acc[mt][ng][1] + bv.y);
            uint32_t p1 = pack_h2(acc[mt][ng][2] + bv.x, acc[mt][ng][3] + bv.y);
            uint32_t v0 = is_t ? tanh_h2(p0) : sigmoid_h2(p0);
            uint32_t v1 = is_t ? tanh_h2(p1) : sigmoid_h2(p1);
            *reinterpret_cast<uint32_t*>(&C[(size_t)r0 * N_OUT + col]) = v0;
            *reinterpret_cast<uint32_t*>(&C[(size_t)(r0 + 8) * N_OUT + col]) = v1;
        }
    }
}

// ---------------- fused fo-pool scan: uint2 lanes (4 j each), block-local two-pass ----
// block = (b, 8 j-quads) x T=512; threads = 8 jq (tid&7) x 32 chunks of 16 (tid>>3).
__global__ __launch_bounds__(256)
void qrnn_scan_fused_kernel(const __half* __restrict__ g, __half* __restrict__ H,
                            float* __restrict__ out, int layer, int write_h) {
    __shared__ float2 Pv[SCH][SJQ][2];
    __shared__ float2 Cv[SCH][SJQ][2];

    const int jq = threadIdx.x & 7;            // 0..7, covers 2 j2 = 4 j
    const int ch = threadIdx.x >> 3;           // 0..31
    const int jcol = blockIdx.x * 32 + jq * 4; // half index (H=800 = 25 blocks * 32)
    const int b = blockIdx.y;

    const __half* gp = g + (size_t)b * N_OUT + jcol;
    const int t0b = ch * STC;

    // phase A: local chunk summary (P, c) for 4 j lanes
    float2 c0 = make_float2(0.f, 0.f), c1 = make_float2(0.f, 0.f);
    float2 P0 = make_float2(1.f, 1.f), P1 = make_float2(1.f, 1.f);
    for (int t0 = t0b; t0 < t0b + STC; t0 += 4) {
#pragma unroll
        for (int u = 0; u < 4; u++) {
            size_t base = (size_t)(t0 + u) * B_DIM * N_OUT;
            uint2 zv = *reinterpret_cast<const uint2*>(gp + base);
            uint2 fv = *reinterpret_cast<const uint2*>(gp + base + H_DIM);
            float2 z0 = h2lo(zv), z1 = h2hi(zv);
            float2 f0 = h2lo(fv), f1 = h2hi(fv);
            c0.x = fmaf(f0.x, z0.x - c0.x, c0.x);
            c0.y = fmaf(f0.y, z0.y - c0.y, c0.y);
            c1.x = fmaf(f1.x, z1.x - c1.x, c1.x);
            c1.y = fmaf(f1.y, z1.y - c1.y, c1.y);
            P0.x *= (1.f - f0.x); P0.y *= (1.f - f0.y);
            P1.x *= (1.f - f1.x); P1.y *= (1.f - f1.y);
        }
    }
    Pv[ch][jq][0] = P0; Pv[ch][jq][1] = P1;
    Cv[ch][jq][0] = c0; Cv[ch][jq][1] = c1;
    __syncthreads();

    // exclusive serial prefix over chunk summaries
    c0 = make_float2(0.f, 0.f); c1 = make_float2(0.f, 0.f);
    for (int i = 0; i < ch; i++) {
        float2 Ca = Cv[i][jq][0], Cb = Cv[i][jq][1];
        float2 Pa = Pv[i][jq][0], Pb = Pv[i][jq][1];
        c0.x = Ca.x + Pa.x * c0.x;
        c0.y = Ca.y + Pa.y * c0.y;
        c1.x = Cb.x + Pb.x * c1.x;
        c1.y = Cb.y + Pb.y * c1.y;
    }

    // phase B: re-scan with correct entering state, write h (uint2)
    for (int t0 = t0b; t0 < t0b + STC; t0 += 4) {
#pragma unroll
        for (int u = 0; u < 4; u++) {
            size_t base = (size_t)(t0 + u) * B_DIM * N_OUT;
            uint2 zv = *reinterpret_cast<const uint2*>(gp + base);
            uint2 fv = *reinterpret_cast<const uint2*>(gp + base + H_DIM);
            uint2 ov = *reinterpret_cast<const uint2*>(gp + base + 2 * H_DIM);
            float2 z0 = h2lo(zv), z1 = h2hi(zv);
            float2 f0 = h2lo(fv), f1 = h2hi(fv);
            float2 o0 = h2lo(ov), o1 = h2hi(ov);
            c0.x = fmaf(f0.x, z0.x - c0.x, c0.x);
            c0.y = fmaf(f0.y, z0.y - c0.y, c0.y);
            c1.x = fmaf(f1.x, z1.x - c1.x, c1.x);
            c1.y = fmaf(f1.y, z1.y - c1.y, c1.y);
            if (write_h) {
                __half2 h0 = __floats2half2_rn(o0.x * c0.x, o0.y * c0.y);
                __half2 h1 = __floats2half2_rn(o1.x * c1.x, o1.y * c1.y);
                uint2 hv;
                hv.x = *reinterpret_cast<uint32_t*>(&h0);
                hv.y = *reinterpret_cast<uint32_t*>(&h1);
                *reinterpret_cast<uint2*>(
                    &H[(size_t)((t0 + u) * B_DIM + b) * KPAD + jcol]) = hv;
            }
        }
    }
    if (ch == SCH - 1) {
        float4 ov = make_float4(c0.x, c0.y, c1.x, c1.y);
        *reinterpret_cast<float4*>(
            &out[(size_t)b * (L_DIM * H_DIM) + (size_t)layer * H_DIM + jcol]) = ov;
    }
}

// ---------------- launch ----------------
extern "C" void kernel_launch(void* const* d_in, const int* in_sizes, int n_in,
                              void* d_out, int out_size) {
    const float* sent = (const float*)d_in[0];
    const float* W0 = (const float*)d_in[2];
    const float* b0 = (const float*)d_in[3];
    const float* W1 = (const float*)d_in[4];
    const float* b1 = (const float*)d_in[5];
    const float* W2 = (const float*)d_in[6];
    const float* b2 = (const float*)d_in[7];
    float* out = (float*)d_out;

    __half* g;  cudaGetSymbolAddress((void**)&g, g_buf);
    __half *a0, *a12, *w0, *w1, *w2;
    cudaGetSymbolAddress((void**)&a0, A0_buf);
    cudaGetSymbolAddress((void**)&a12, A12_buf);
    cudaGetSymbolAddress((void**)&w0, W0_buf);
    cudaGetSymbolAddress((void**)&w1, W1_buf);
    cudaGetSymbolAddress((void**)&w2, W2_buf);

    cudaFuncSetAttribute(qrnn_gemm_kernel, cudaFuncAttributeMaxDynamicSharedMemorySize,
                         STAGES * STAGE_BYTES);

    {
        dim3 wblk(32, 8);
        dim3 wgrid(N_PADROWS / 32, KPAD / 32, 3);
        conv_w_all_kernel<<<wgrid, wblk>>>(W0, W1, W2, w0, w1, w2);
    }
    {
        int n = M_DIM * (KPAD0 / 4);
        conv_sent_kernel<<<(n + 255) / 256, 256>>>(sent);
    }

    dim3 ggrid(N_PADROWS / BN, M_DIM / BM);   // (19, 256)
    size_t smem = STAGES * STAGE_BYTES;
    dim3 sgrid(H_DIM / 32, B_DIM);            // (25, 64)

    qrnn_gemm_kernel<<<ggrid, 256, smem>>>(a0, w0, KPAD0, KPAD0 / BK, b0, g);
    qrnn_scan_fused_kernel<<<sgrid, 256>>>(g, a12, out, 0, 1);

    qrnn_gemm_kernel<<<ggrid, 256, smem>>>(a12, w1, KPAD, KPAD / BK, b1, g);
    qrnn_scan_fused_kernel<<<sgrid, 256>>>(g, a12, out, 1, 1);

    qrnn_gemm_kernel<<<ggrid, 256, smem>>>(a12, w2, KPAD, KPAD / BK, b2, g);
    qrnn_scan_fused_kernel<<<sgrid, 256>>>(g, a12, out, 2, 0);
}